// round 3
// baseline (speedup 1.0000x reference)
#include <cuda_runtime.h>

typedef unsigned long long u64;

// ---- f32x2 packed math (lanes = two samples) ----
__device__ __forceinline__ u64 pk2(float lo, float hi) {
    u64 d; asm("mov.b64 %0, {%1, %2};" : "=l"(d) : "f"(lo), "f"(hi)); return d;
}
__device__ __forceinline__ void upk2(float& lo, float& hi, u64 v) {
    asm("mov.b64 {%0, %1}, %2;" : "=f"(lo), "=f"(hi) : "l"(v));
}
__device__ __forceinline__ u64 mul2(u64 a, u64 b) {
    u64 d; asm("mul.rn.f32x2 %0, %1, %2;" : "=l"(d) : "l"(a), "l"(b)); return d;
}
__device__ __forceinline__ u64 fma2(u64 a, u64 b, u64 c) {
    u64 d; asm("fma.rn.f32x2 %0, %1, %2, %3;" : "=l"(d) : "l"(a), "l"(b), "l"(c)); return d;
}

// Pauli-propagated term table (compile-time circuit algebra; see derivation):
// z_q = sum_t sgn * prod_j [cs: C_j or S_j] * [rz: cos(b_j) or sin(b_j)] * monomial(cos a_j, sin a_j)
// cs[j]: 0=none 1=cos(w1y_j) 2=sin(w1y_j);  rz[j]: 0=none 1=cos(w0z_j) 2=sin(w0z_j)
struct Term { signed char sgn; signed char cs[4]; signed char rz[4]; };
__constant__ Term TERMS[36] = {
    // z0 (string Z1Z2Z3)
    {+1,{0,1,1,1},{0,0,0,0}}, {-1,{0,1,1,2},{1,1,0,1}}, {+1,{0,1,2,1},{0,0,2,2}}, {-1,{0,1,2,2},{2,2,1,0}},
    {-1,{0,2,1,1},{0,1,1,0}}, {-1,{0,2,1,2},{2,0,2,1}}, {-1,{0,2,2,1},{0,2,0,2}}, {-1,{0,2,2,2},{1,0,0,0}},
    // z1 (string Z0Z1)
    {+1,{1,1,0,0},{0,0,0,0}}, {+1,{1,2,0,0},{0,2,2,0}}, {+1,{2,1,0,0},{2,2,0,0}}, {+1,{2,2,0,0},{1,0,1,0}},
    // z2 (string Z0Z1Z2)
    {+1,{1,1,1,0},{0,0,0,0}}, {+1,{1,1,2,0},{0,0,2,2}}, {-1,{1,2,1,0},{0,1,1,0}}, {-1,{1,2,2,0},{0,2,0,2}},
    {-1,{2,1,1,0},{1,1,0,0}}, {-1,{2,1,2,0},{2,2,1,1}}, {-1,{2,2,1,0},{2,0,2,0}}, {-1,{2,2,2,0},{1,0,0,1}},
    // z3 (string Z0Z1Z2Z3)
    {+1,{1,1,1,1},{0,0,0,0}}, {+1,{1,1,1,2},{1,2,0,2}}, {-1,{1,1,2,1},{0,0,1,1}}, {-1,{1,1,2,2},{2,1,2,0}},
    {+1,{1,2,1,1},{0,2,2,0}}, {-1,{1,2,1,2},{2,0,1,2}}, {+1,{1,2,2,1},{0,1,0,1}}, {-1,{1,2,2,2},{1,0,0,0}},
    {+1,{2,1,1,1},{2,2,0,0}}, {+1,{2,1,1,2},{0,0,0,1}}, {-1,{2,1,2,1},{1,1,2,2}}, {-1,{2,1,2,2},{0,0,1,0}},
    {+1,{2,2,1,1},{1,0,1,0}}, {+1,{2,2,1,2},{0,2,2,1}}, {+1,{2,2,2,1},{2,0,0,2}}, {+1,{2,2,2,2},{0,1,0,0}},
};

__global__ void __launch_bounds__(256) qsim_kernel(const float* __restrict__ x,
                                                   const float* __restrict__ w,
                                                   float* __restrict__ out, int B) {
    __shared__ float s_w0y[4];        // layer-0 RY weights (add to embedding angle)
    __shared__ float s_C[4], s_S[4];  // cos/sin of layer-1 RY weights
    __shared__ float s_cb[4], s_sb[4];// cos/sin of layer-0 RZ weights
    __shared__ u64   s_K[36];         // folded term coefficients, both lanes

    const int tid = threadIdx.x;
    if (tid < 4) {
        const int q = tid;
        s_w0y[q] = w[2 * q];
        float sv, cv;
        sincosf(w[8 + 2 * q], &sv, &cv);  // layer-1 RY full angle
        s_C[q] = cv; s_S[q] = sv;
        sincosf(w[2 * q + 1], &sv, &cv);  // layer-0 RZ full angle
        s_cb[q] = cv; s_sb[q] = sv;
    }
    __syncthreads();
    if (tid < 36) {
        Term T = TERMS[tid];
        float k = (float)T.sgn;
#pragma unroll
        for (int j = 0; j < 4; ++j) {
            if (T.cs[j] == 1) k *= s_C[j]; else if (T.cs[j] == 2) k *= s_S[j];
            if (T.rz[j] == 1) k *= s_cb[j]; else if (T.rz[j] == 2) k *= s_sb[j];
        }
        s_K[tid] = pk2(k, k);
    }
    __syncthreads();

    const int b0 = 2 * (blockIdx.x * 256 + tid);
    const int b1 = b0 + 1;
    if (b0 >= B) return;

    // load two x rows (stride 8 floats; only first 4 used)
    const float4* X4 = reinterpret_cast<const float4*>(x);
    float4 xa = X4[2 * b0];
    float4 xb = (b1 < B) ? X4[2 * b1] : xa;
    float x0a[4] = {xa.x, xa.y, xa.z, xa.w};
    float x0b[4] = {xb.x, xb.y, xb.z, xb.w};

    // per-qubit packed (cos a, sin a) over the two samples; a = pi*tanh(x)+w0y
    u64 Z[4], X[4];
    const float PI = 3.14159265358979323846f;
#pragma unroll
    for (int q = 0; q < 4; ++q) {
        float ea = __expf(2.0f * x0a[q]);
        float eb = __expf(2.0f * x0b[q]);
        float ta = 1.0f - __fdividef(2.0f, ea + 1.0f);
        float tb = 1.0f - __fdividef(2.0f, eb + 1.0f);
        float aa = fmaf(ta, PI, s_w0y[q]);
        float ab = fmaf(tb, PI, s_w0y[q]);
        float sa, ca, sb2, cb2;
        __sincosf(aa, &sa, &ca);
        __sincosf(ab, &sb2, &cb2);
        Z[q] = pk2(ca, cb2);
        X[q] = pk2(sa, sb2);
    }

    // front/back pair products
    u64 fzz = mul2(Z[0], Z[1]), fzx = mul2(Z[0], X[1]);
    u64 fxz = mul2(X[0], Z[1]), fxx = mul2(X[0], X[1]);
    u64 bzz = mul2(Z[2], Z[3]), bzx = mul2(Z[2], X[3]);
    u64 bxz = mul2(X[2], Z[3]), bxx = mul2(X[2], X[3]);

    // ---- z0 ----
    u64 acc0 = fma2(s_K[0], mul2(fzz, Z[3]), mul2(s_K[2], bxx));
    acc0 = fma2(s_K[1], mul2(fxx, bzx), acc0);
    acc0 = fma2(s_K[3], mul2(fxx, X[2]), acc0);
    acc0 = fma2(s_K[4], mul2(X[1], bxz), acc0);
    acc0 = fma2(s_K[5], mul2(fxz, bxx), acc0);
    acc0 = fma2(s_K[6], mul2(fzx, bzx), acc0);
    acc0 = fma2(s_K[7], X[0], acc0);

    // ---- z1 ----
    u64 acc1 = fma2(s_K[8], mul2(Z[0], bzz), mul2(s_K[10], fxx));
    acc1 = fma2(s_K[9],  mul2(X[1], bxz), acc1);
    acc1 = fma2(s_K[11], mul2(X[0], X[2]), acc1);

    // ---- z2 ----
    u64 acc2 = fma2(s_K[12], mul2(Z[1], Z[3]), mul2(s_K[19], mul2(X[0], X[3])));
    acc2 = fma2(s_K[13], mul2(Z[0], bxx), acc2);
    acc2 = fma2(s_K[14], mul2(fzx, bxz), acc2);
    acc2 = fma2(s_K[15], mul2(X[1], bzx), acc2);
    acc2 = fma2(s_K[16], mul2(fxx, Z[2]), acc2);
    acc2 = fma2(s_K[17], mul2(fxx, bxx), acc2);
    acc2 = fma2(s_K[18], mul2(fxz, X[2]), acc2);

    // ---- z3 ----
    u64 acc3 = fma2(s_K[20], mul2(Z[0], Z[2]), mul2(s_K[29], bzx));
    acc3 = fma2(s_K[21], mul2(fxx, X[3]), acc3);
    acc3 = fma2(s_K[22], mul2(Z[1], bxx), acc3);
    acc3 = fma2(s_K[23], mul2(fxx, bxz), acc3);
    acc3 = fma2(s_K[24], mul2(X[1], X[2]), acc3);
    acc3 = fma2(s_K[25], mul2(X[0], bxx), acc3);
    acc3 = fma2(s_K[26], mul2(fzx, X[3]), acc3);
    acc3 = fma2(s_K[27], mul2(fxz, bzz), acc3);
    acc3 = fma2(s_K[28], mul2(fxx, Z[3]), acc3);
    acc3 = fma2(s_K[30], mul2(fxx, bxx), acc3);
    acc3 = fma2(s_K[31], mul2(fzz, X[2]), acc3);
    acc3 = fma2(s_K[32], mul2(X[0], bxz), acc3);
    acc3 = fma2(s_K[33], mul2(fzx, bxx), acc3);
    acc3 = fma2(s_K[34], mul2(fxz, bzx), acc3);
    acc3 = fma2(s_K[35], X[1], acc3);

    float z0a, z0b, z1a, z1b, z2a, z2b, z3a, z3b;
    upk2(z0a, z0b, acc0);
    upk2(z1a, z1b, acc1);
    upk2(z2a, z2b, acc2);
    upk2(z3a, z3b, acc3);

    float4* O4 = reinterpret_cast<float4*>(out);
    float4 oa; oa.x = z0a; oa.y = z1a; oa.z = z2a; oa.w = z3a;
    O4[b0] = oa;
    if (b1 < B) {
        float4 ob; ob.x = z0b; ob.y = z1b; ob.z = z2b; ob.w = z3b;
        O4[b1] = ob;
    }
}

extern "C" void kernel_launch(void* const* d_in, const int* in_sizes, int n_in,
                              void* d_out, int out_size) {
    const float* x = (const float*)d_in[0];
    const float* w = (const float*)d_in[1];
    float* out = (float*)d_out;
    const int B = in_sizes[0] / 8;

    const int threads = 256;
    const int blocks = (B + 2 * threads - 1) / (2 * threads);
    qsim_kernel<<<blocks, threads>>>(x, w, out, B);
}

// round 4
// speedup vs baseline: 1.0194x; 1.0194x over previous
#include <cuda_runtime.h>

// Pauli-propagated term table (compile-time circuit algebra, verified R3 rel_err 6e-7):
// z_q = sum_t sgn * prod_j [cs: C_j or S_j] * [rz: cos(b_j) or sin(b_j)] * monomial(cos a_j, sin a_j)
// cs[j]: 0=none 1=cos(w1y_j) 2=sin(w1y_j);  rz[j]: 0=none 1=cos(w0z_j) 2=sin(w0z_j)
struct Term { signed char sgn; signed char cs[4]; signed char rz[4]; };
__constant__ Term TERMS[36] = {
    // z0 (string Z1Z2Z3)
    {+1,{0,1,1,1},{0,0,0,0}}, {-1,{0,1,1,2},{1,1,0,1}}, {+1,{0,1,2,1},{0,0,2,2}}, {-1,{0,1,2,2},{2,2,1,0}},
    {-1,{0,2,1,1},{0,1,1,0}}, {-1,{0,2,1,2},{2,0,2,1}}, {-1,{0,2,2,1},{0,2,0,2}}, {-1,{0,2,2,2},{1,0,0,0}},
    // z1 (string Z0Z1)
    {+1,{1,1,0,0},{0,0,0,0}}, {+1,{1,2,0,0},{0,2,2,0}}, {+1,{2,1,0,0},{2,2,0,0}}, {+1,{2,2,0,0},{1,0,1,0}},
    // z2 (string Z0Z1Z2)
    {+1,{1,1,1,0},{0,0,0,0}}, {+1,{1,1,2,0},{0,0,2,2}}, {-1,{1,2,1,0},{0,1,1,0}}, {-1,{1,2,2,0},{0,2,0,2}},
    {-1,{2,1,1,0},{1,1,0,0}}, {-1,{2,1,2,0},{2,2,1,1}}, {-1,{2,2,1,0},{2,0,2,0}}, {-1,{2,2,2,0},{1,0,0,1}},
    // z3 (string Z0Z1Z2Z3)
    {+1,{1,1,1,1},{0,0,0,0}}, {+1,{1,1,1,2},{1,2,0,2}}, {-1,{1,1,2,1},{0,0,1,1}}, {-1,{1,1,2,2},{2,1,2,0}},
    {+1,{1,2,1,1},{0,2,2,0}}, {-1,{1,2,1,2},{2,0,1,2}}, {+1,{1,2,2,1},{0,1,0,1}}, {-1,{1,2,2,2},{1,0,0,0}},
    {+1,{2,1,1,1},{2,2,0,0}}, {+1,{2,1,1,2},{0,0,0,1}}, {-1,{2,1,2,1},{1,1,2,2}}, {-1,{2,1,2,2},{0,0,1,0}},
    {+1,{2,2,1,1},{1,0,1,0}}, {+1,{2,2,1,2},{0,2,2,1}}, {+1,{2,2,2,1},{2,0,0,2}}, {+1,{2,2,2,2},{0,1,0,0}},
};

__global__ void __launch_bounds__(256) qsim_kernel(const float* __restrict__ x,
                                                   const float* __restrict__ w,
                                                   float* __restrict__ out, int B) {
    __shared__ float s_w0y[4];   // layer-0 RY weights (added to embedding angle)
    __shared__ float s_K[36];    // folded weight-only term coefficients

    const int tid = threadIdx.x;
    {
        __shared__ float s_C[4], s_S[4], s_cb[4], s_sb[4];
        if (tid < 4) {
            const int q = tid;
            s_w0y[q] = w[2 * q];
            float sv, cv;
            sincosf(w[8 + 2 * q], &sv, &cv);  // layer-1 RY full angle
            s_C[q] = cv; s_S[q] = sv;
            sincosf(w[2 * q + 1], &sv, &cv);  // layer-0 RZ full angle
            s_cb[q] = cv; s_sb[q] = sv;
        }
        __syncthreads();
        if (tid < 36) {
            Term T = TERMS[tid];
            float k = (float)T.sgn;
#pragma unroll
            for (int j = 0; j < 4; ++j) {
                if (T.cs[j] == 1) k *= s_C[j]; else if (T.cs[j] == 2) k *= s_S[j];
                if (T.rz[j] == 1) k *= s_cb[j]; else if (T.rz[j] == 2) k *= s_sb[j];
            }
            s_K[tid] = k;
        }
        __syncthreads();
    }

    const int b = blockIdx.x * 256 + tid;
    if (b >= B) return;

    // one x row (8 floats, first 4 used); coalesced float4 load
    float4 xv = reinterpret_cast<const float4*>(x)[2 * b];
    float xin[4] = {xv.x, xv.y, xv.z, xv.w};

    // per-qubit (cos a, sin a), a = pi*tanh(x_q) + w0y_q ; 4 independent MUFU chains
    float Z[4], X[4];
    const float PI = 3.14159265358979323846f;
#pragma unroll
    for (int q = 0; q < 4; ++q) {
        float e = __expf(2.0f * xin[q]);
        float t = 1.0f - __fdividef(2.0f, e + 1.0f);  // tanh, ~1e-6 abs err
        float a = fmaf(t, PI, s_w0y[q]);
        __sincosf(a, &X[q], &Z[q]);
    }

    // front/back pair products
    float fzz = Z[0] * Z[1], fzx = Z[0] * X[1], fxz = X[0] * Z[1], fxx = X[0] * X[1];
    float bzz = Z[2] * Z[3], bzx = Z[2] * X[3], bxz = X[2] * Z[3], bxx = X[2] * X[3];

    // ---- z0 ----
    float g0 = fmaf(s_K[1], bzx, s_K[3] * X[2]);           // fxx group
    float z0 = fmaf(s_K[0] * fzz, Z[3], s_K[2] * bxx);
    z0 = fmaf(fxx, g0, z0);
    z0 = fmaf(s_K[4] * X[1], bxz, z0);
    z0 = fmaf(s_K[5] * fxz, bxx, z0);
    z0 = fmaf(s_K[6] * fzx, bzx, z0);
    z0 = fmaf(s_K[7], X[0], z0);

    // ---- z1 ----
    float z1 = fmaf(s_K[8] * Z[0], bzz, s_K[10] * fxx);
    z1 = fmaf(s_K[9] * X[1], bxz, z1);
    z1 = fmaf(s_K[11] * X[0], X[2], z1);

    // ---- z2 ----
    float g2 = fmaf(s_K[16], Z[2], s_K[17] * bxx);         // fxx group
    float z2 = fmaf(s_K[12] * Z[1], Z[3], s_K[19] * X[0] * X[3]);
    z2 = fmaf(fxx, g2, z2);
    z2 = fmaf(s_K[13] * Z[0], bxx, z2);
    z2 = fmaf(s_K[14] * fzx, bxz, z2);
    z2 = fmaf(s_K[15] * X[1], bzx, z2);
    z2 = fmaf(s_K[18] * fxz, X[2], z2);

    // ---- z3 ----
    float g3 = fmaf(s_K[21], X[3], s_K[23] * bxz);         // fxx group
    g3 = fmaf(s_K[28], Z[3], g3);
    g3 = fmaf(s_K[30], bxx, g3);
    float z3 = fmaf(s_K[20] * Z[0], Z[2], s_K[29] * bzx);
    z3 = fmaf(fxx, g3, z3);
    z3 = fmaf(s_K[22] * Z[1], bxx, z3);
    z3 = fmaf(s_K[24] * X[1], X[2], z3);
    z3 = fmaf(s_K[25] * X[0], bxx, z3);
    z3 = fmaf(s_K[26] * fzx, X[3], z3);
    z3 = fmaf(s_K[27] * fxz, bzz, z3);
    z3 = fmaf(s_K[31] * fzz, X[2], z3);
    z3 = fmaf(s_K[32] * X[0], bxz, z3);
    z3 = fmaf(s_K[33] * fzx, bxx, z3);
    z3 = fmaf(s_K[34] * fxz, bzx, z3);
    z3 = fmaf(s_K[35], X[1], z3);

    float4 o; o.x = z0; o.y = z1; o.z = z2; o.w = z3;
    reinterpret_cast<float4*>(out)[b] = o;
}

extern "C" void kernel_launch(void* const* d_in, const int* in_sizes, int n_in,
                              void* d_out, int out_size) {
    const float* x = (const float*)d_in[0];
    const float* w = (const float*)d_in[1];
    float* out = (float*)d_out;
    const int B = in_sizes[0] / 8;

    qsim_kernel<<<(B + 255) / 256, 256>>>(x, w, out, B);
}